// round 1
// baseline (speedup 1.0000x reference)
#include <cuda_runtime.h>

#define N 512
#define ROWS_PER_BLOCK 4

// Closed form for the Givens-rotation chain (rotations on columns (i,i+1),
// applied for i = N-2 down to 0, theta index == i):
//   U[r][j]   = 0                                        for j > r+1
//   U[r][r+1] = s_r
//   U[r][j]   = c'_r * c_{j-1} * prod_{m=j}^{r-1} (-s_m) for j <= r
// with c_{-1} = 1 and c'_{N-1} = 1.
__global__ __launch_bounds__(N) void unitary_closed_form_kernel(
    const float* __restrict__ thetas,  // K = N-1 = 511 angles
    float* __restrict__ out)           // N x N row-major fp32
{
    __shared__ float sh_s[N];  // sin(theta_j), sh_s[N-1] = 0
    __shared__ float sh_c[N];  // cos(theta_j), sh_c[N-1] = 1 (c'_{N-1})
    __shared__ float sh_a[N];  // scan buffer for suffix products

    const int j  = threadIdx.x;                    // column index
    const int r0 = blockIdx.x * ROWS_PER_BLOCK;    // first row of this block

    float sj = 0.0f, cj = 1.0f;
    if (j < N - 1) {
        sincosf(thetas[j], &sj, &cj);
    }
    sh_s[j] = sj;
    sh_c[j] = cj;

    // Scan input: a_m = -s_m for m in [0, r0), else 1.
    // After suffix-product scan: sh_a[j] = prod_{m=j}^{r0-1} (-s_m)  (= 1 if j >= r0)
    sh_a[j] = (j < r0) ? -sj : 1.0f;
    __syncthreads();

    #pragma unroll
    for (int off = 1; off < N; off <<= 1) {
        float v = sh_a[j];
        if (j + off < N) v *= sh_a[j + off];
        __syncthreads();
        sh_a[j] = v;
        __syncthreads();
    }

    // x carries c_{j-1} * prod_{m=j}^{r-1}(-s_m) as r advances.
    const float cm1   = (j > 0) ? sh_c[j - 1] : 1.0f;
    const float sprev = (j > 0) ? sh_s[j - 1] : 0.0f;
    float x = cm1 * sh_a[j];

    float* row = out + (size_t)r0 * N + j;
    #pragma unroll
    for (int k = 0; k < ROWS_PER_BLOCK; ++k) {
        const int r = r0 + k;
        float val;
        if (j <= r) {
            val = sh_c[r] * x;      // sh_c[N-1] == 1 handles r = N-1
            x *= -sh_s[r];          // sh_s[N-1] == 0, x unused afterwards
        } else if (j == r + 1) {
            val = sprev;            // superdiagonal: s_{r}
        } else {
            val = 0.0f;             // strict upper zero region
        }
        row[0] = val;               // coalesced: consecutive j -> consecutive addr
        row += N;
    }
}

extern "C" void kernel_launch(void* const* d_in, const int* in_sizes, int n_in,
                              void* d_out, int out_size) {
    (void)in_sizes; (void)n_in; (void)out_size;
    const float* thetas = (const float*)d_in[0];
    float* out = (float*)d_out;
    unitary_closed_form_kernel<<<N / ROWS_PER_BLOCK, N>>>(thetas, out);
}